// round 7
// baseline (speedup 1.0000x reference)
#include <cuda_runtime.h>
#include <cstdint>

// QuantizationLayer: out[i*4 + {0..3}] = bits (MSB-first) of round_half_even(x[i]*16 - 0.5)
// x: (32768, 512) f32 in [0,1)  ->  out: (32768, 2048) f32 of {0.0, 1.0}
//
// Streaming kernel at the mixed read/write HBM ceiling (~6.4 TB/s effective).
// Each thread: 2 pairs (4 elements). Per pair: one float2 load (512B/warp
// LDG.64) -> one 256-bit v8 store (2KB/warp STG.256). 512-thread blocks to
// halve CTA count / scheduling overhead. Loads .cs (read-once); stores
// default write-back.

#define THREADS 512
#define PAIRS_PER_THREAD 2                      // 2 pairs = 4 elements/thread
#define TILE_PAIRS (THREADS * PAIRS_PER_THREAD) // 1024 pairs = 2048 elems/block

__device__ __forceinline__ void quant_pair_store(float2 v, float* gptr) {
    int c0 = ((int)rintf(fmaf(v.x, 16.0f, -0.5f))) & 15;
    int c1 = ((int)rintf(fmaf(v.y, 16.0f, -0.5f))) & 15;

    float b0 = (float)((c0 >> 3) & 1);
    float b1 = (float)((c0 >> 2) & 1);
    float b2 = (float)((c0 >> 1) & 1);
    float b3 = (float)(c0 & 1);
    float b4 = (float)((c1 >> 3) & 1);
    float b5 = (float)((c1 >> 2) & 1);
    float b6 = (float)((c1 >> 1) & 1);
    float b7 = (float)(c1 & 1);

#if __CUDA_ARCH__ >= 1000
    asm volatile(
        "st.global.v8.f32 [%0], {%1, %2, %3, %4, %5, %6, %7, %8};"
        :: "l"(gptr),
           "f"(b0), "f"(b1), "f"(b2), "f"(b3),
           "f"(b4), "f"(b5), "f"(b6), "f"(b7)
        : "memory");
#else
    ((float4*)gptr)[0] = make_float4(b0, b1, b2, b3);
    ((float4*)gptr)[1] = make_float4(b4, b5, b6, b7);
#endif
}

__global__ void __launch_bounds__(THREADS)
quant_unpack_kernel(const float2* __restrict__ x2,
                    float* __restrict__ out,
                    int n_pairs) {
    int base = blockIdx.x * TILE_PAIRS + threadIdx.x;

    if (base + (PAIRS_PER_THREAD - 1) * THREADS < n_pairs) {
        // Fast path (always taken for n = 16,777,216)
        float2 v[PAIRS_PER_THREAD];
#pragma unroll
        for (int k = 0; k < PAIRS_PER_THREAD; k++)
            v[k] = __ldcs(x2 + base + k * THREADS);

#pragma unroll
        for (int k = 0; k < PAIRS_PER_THREAD; k++) {
            int p = base + k * THREADS;
            quant_pair_store(v[k], out + (size_t)p * 8);
        }
    } else {
        // Tail path
#pragma unroll
        for (int k = 0; k < PAIRS_PER_THREAD; k++) {
            int p = base + k * THREADS;
            if (p >= n_pairs) continue;
            float2 v = __ldcs(x2 + p);
            quant_pair_store(v, out + (size_t)p * 8);
        }
    }
}

extern "C" void kernel_launch(void* const* d_in, const int* in_sizes, int n_in,
                              void* d_out, int out_size) {
    const float* x = (const float*)d_in[0];
    float* out = (float*)d_out;
    int n = in_sizes[0];        // 16,777,216 (even)
    int n_pairs = n >> 1;       // 8,388,608

    int blocks = (n_pairs + TILE_PAIRS - 1) / TILE_PAIRS;  // 8192
    quant_unpack_kernel<<<blocks, THREADS>>>((const float2*)x, out, n_pairs);
}